// round 1
// baseline (speedup 1.0000x reference)
#include <cuda_runtime.h>
#include <math.h>

#define Lc 4
#define Bc 256
#define Sc 256
#define Hc 1024
#define Kc 64
#define SPLIT 8
#define SROWS (Sc / SPLIT)   // 32

// Scratch: partial masked sums, [B][SPLIT][H] fp32 = 8 MB
__device__ float g_partial[(size_t)Bc * SPLIT * Hc];

__device__ __forceinline__ float gelu_exact(float x) {
    return 0.5f * x * (1.0f + erff(x * 0.70710678118654752f));
}

__device__ __forceinline__ float warp_sum(float v) {
    #pragma unroll
    for (int o = 16; o; o >>= 1) v += __shfl_down_sync(0xffffffffu, v, o);
    return v;
}

// ---------------------------------------------------------------------------
// Kernel 1: weighted-layer pooling + masked sum over an S-chunk.
// grid = (SPLIT, B), block = 256. Each thread owns 4 consecutive h (float4).
// ---------------------------------------------------------------------------
__global__ __launch_bounds__(256) void pool_kernel(
    const float* __restrict__ hidden,   // [L,B,S,H]
    const int*   __restrict__ mask,     // [B,S]
    const float* __restrict__ lw)       // [L]
{
    const int j = blockIdx.x;       // S-chunk
    const int b = blockIdx.y;
    const int t = threadIdx.x;      // 0..255

    // softmax over layer weights (tiny, recomputed per thread, L1/L2 cached)
    float l0 = lw[0], l1 = lw[1], l2 = lw[2], l3 = lw[3];
    float mx = fmaxf(fmaxf(l0, l1), fmaxf(l2, l3));
    float w0 = expf(l0 - mx), w1 = expf(l1 - mx), w2 = expf(l2 - mx), w3 = expf(l3 - mx);
    float winv = 1.0f / (w0 + w1 + w2 + w3);
    w0 *= winv; w1 *= winv; w2 *= winv; w3 *= winv;

    __shared__ int sm[SROWS];
    if (t < SROWS) sm[t] = mask[b * Sc + j * SROWS + t];
    __syncthreads();

    const size_t LSTRIDE4 = (size_t)Bc * Sc * (Hc / 4);   // per-layer stride in float4
    const float4* base = reinterpret_cast<const float4*>(hidden)
                       + ((size_t)b * Sc + (size_t)j * SROWS) * (Hc / 4) + t;

    float4 acc = make_float4(0.f, 0.f, 0.f, 0.f);

    #pragma unroll 4
    for (int s = 0; s < SROWS; s++) {
        if (sm[s]) {
            const float4* p = base + (size_t)s * (Hc / 4);
            float4 x0 = __ldg(p);
            float4 x1 = __ldg(p + LSTRIDE4);
            float4 x2 = __ldg(p + 2 * LSTRIDE4);
            float4 x3 = __ldg(p + 3 * LSTRIDE4);
            acc.x += w0 * x0.x + w1 * x1.x + w2 * x2.x + w3 * x3.x;
            acc.y += w0 * x0.y + w1 * x1.y + w2 * x2.y + w3 * x3.y;
            acc.z += w0 * x0.z + w1 * x1.z + w2 * x2.z + w3 * x3.z;
            acc.w += w0 * x0.w + w1 * x1.w + w2 * x2.w + w3 * x3.w;
        }
    }

    reinterpret_cast<float4*>(g_partial)[((size_t)b * SPLIT + j) * (Hc / 4) + t] = acc;
}

// ---------------------------------------------------------------------------
// Kernel 2: per-sample finalize — mean, section-routed adapter, heads.
// grid = B, block = 256.
// ---------------------------------------------------------------------------
__global__ __launch_bounds__(256) void finalize_kernel(
    const int*   __restrict__ mask,        // [B,S]
    const int*   __restrict__ section_id,  // [B]
    const float* __restrict__ Wd,          // [N_SEC,H,K]
    const float* __restrict__ bd,          // [N_SEC,K]
    const float* __restrict__ Wu,          // [N_SEC,K,H]
    const float* __restrict__ bu,          // [N_SEC,H]
    const float* __restrict__ Wreg,        // [H,1]
    const float* __restrict__ breg,        // [1]
    const float* __restrict__ Word,        // [H,4]
    const float* __restrict__ bord,        // [4]
    float*       __restrict__ out)         // [B] reg ++ [B,4] ord
{
    const int b = blockIdx.x;
    const int t = threadIdx.x;

    __shared__ float feats[Hc];
    __shared__ float hk[Kc];
    __shared__ float red[256];
    __shared__ float wr[5][8];

    // ---- mask count (S == blockDim, one element per thread) ----
    float mv = (float)mask[b * Sc + t];
    mv = warp_sum(mv);
    if ((t & 31) == 0) red[t >> 5] = mv;
    __syncthreads();
    if (t == 0) {
        float s = 0.f;
        #pragma unroll
        for (int i = 0; i < 8; i++) s += red[i];
        red[0] = s;
    }
    __syncthreads();
    const float invm = 1.0f / fmaxf(red[0], 1e-6f);
    __syncthreads();   // red reused below

    // ---- gather partials -> feats ----
    const float* pp = g_partial + (size_t)b * SPLIT * Hc;
    for (int h = t; h < Hc; h += 256) {
        float acc = 0.f;
        #pragma unroll
        for (int jj = 0; jj < SPLIT; jj++) acc += pp[jj * Hc + h];
        feats[h] = acc * invm;
    }
    __syncthreads();

    const int sec = section_id[b];

    // ---- down-proj + GeLU: hk[k] = gelu(sum_h feats[h]*Wd[h,k] + bd[k]) ----
    {
        const float* wd = Wd + (size_t)sec * Hc * Kc;
        const int k = t & 63;
        const int c = t >> 6;                 // 4 h-chunks of 256
        const float* wp = wd + (size_t)(c * 256) * Kc + k;
        float a0 = 0.f, a1 = 0.f, a2 = 0.f, a3 = 0.f;
        #pragma unroll 4
        for (int h = 0; h < 256; h += 4) {
            a0 += feats[c * 256 + h + 0] * wp[(h + 0) * Kc];
            a1 += feats[c * 256 + h + 1] * wp[(h + 1) * Kc];
            a2 += feats[c * 256 + h + 2] * wp[(h + 2) * Kc];
            a3 += feats[c * 256 + h + 3] * wp[(h + 3) * Kc];
        }
        red[t] = (a0 + a1) + (a2 + a3);
        __syncthreads();
        if (t < Kc) {
            float x = red[t] + red[t + 64] + red[t + 128] + red[t + 192] + bd[sec * Kc + t];
            hk[t] = gelu_exact(x);
        }
        __syncthreads();
    }

    // ---- up-proj residual + heads ----
    const float* wu  = Wu + (size_t)sec * Kc * Hc;
    const float* buv = bu + (size_t)sec * Hc;
    float preg = 0.f, po0 = 0.f, po1 = 0.f, po2 = 0.f, po3 = 0.f;

    for (int h = t; h < Hc; h += 256) {
        float a0 = 0.f, a1 = 0.f, a2 = 0.f, a3 = 0.f;
        #pragma unroll
        for (int k = 0; k < Kc; k += 4) {
            a0 += hk[k + 0] * wu[(size_t)(k + 0) * Hc + h];
            a1 += hk[k + 1] * wu[(size_t)(k + 1) * Hc + h];
            a2 += hk[k + 2] * wu[(size_t)(k + 2) * Hc + h];
            a3 += hk[k + 3] * wu[(size_t)(k + 3) * Hc + h];
        }
        float f2 = feats[h] + buv[h] + (a0 + a1) + (a2 + a3);
        preg += f2 * Wreg[h];
        po0  += f2 * Word[h * 4 + 0];
        po1  += f2 * Word[h * 4 + 1];
        po2  += f2 * Word[h * 4 + 2];
        po3  += f2 * Word[h * 4 + 3];
    }

    preg = warp_sum(preg);
    po0  = warp_sum(po0);
    po1  = warp_sum(po1);
    po2  = warp_sum(po2);
    po3  = warp_sum(po3);
    if ((t & 31) == 0) {
        int w = t >> 5;
        wr[0][w] = preg; wr[1][w] = po0; wr[2][w] = po1; wr[3][w] = po2; wr[4][w] = po3;
    }
    __syncthreads();
    if (t == 0) {
        float r = 0.f, o0 = 0.f, o1 = 0.f, o2 = 0.f, o3 = 0.f;
        #pragma unroll
        for (int i = 0; i < 8; i++) {
            r  += wr[0][i]; o0 += wr[1][i]; o1 += wr[2][i]; o2 += wr[3][i]; o3 += wr[4][i];
        }
        out[b] = r + breg[0];
        float* op = out + Bc + (size_t)b * 4;
        op[0] = o0 + bord[0];
        op[1] = o1 + bord[1];
        op[2] = o2 + bord[2];
        op[3] = o3 + bord[3];
    }
}

extern "C" void kernel_launch(void* const* d_in, const int* in_sizes, int n_in,
                              void* d_out, int out_size)
{
    const float* hidden = (const float*)d_in[0];
    const int*   mask   = (const int*)  d_in[1];
    const int*   sec    = (const int*)  d_in[2];
    const float* lw     = (const float*)d_in[3];
    const float* Wd     = (const float*)d_in[4];
    const float* bd     = (const float*)d_in[5];
    const float* Wu     = (const float*)d_in[6];
    const float* bu     = (const float*)d_in[7];
    const float* Wreg   = (const float*)d_in[8];
    const float* breg   = (const float*)d_in[9];
    const float* Word   = (const float*)d_in[10];
    const float* bord   = (const float*)d_in[11];
    float* out = (float*)d_out;

    dim3 grid(SPLIT, Bc);
    pool_kernel<<<grid, 256>>>(hidden, mask, lw);
    finalize_kernel<<<Bc, 256>>>(mask, sec, Wd, bd, Wu, bu,
                                 Wreg, breg, Word, bord, out);
}

// round 2
// speedup vs baseline: 1.1837x; 1.1837x over previous
#include <cuda_runtime.h>
#include <math.h>

#define Lc 4
#define Bc 256
#define Sc 256
#define Hc 1024
#define Kc 64
#define SPLIT 8
#define SROWS (Sc / SPLIT)   // 32

// Scratch: partial masked sums, [B][SPLIT][H] fp32 = 8 MB
__device__ float g_partial[(size_t)Bc * SPLIT * Hc];

__device__ __forceinline__ float gelu_exact(float x) {
    return 0.5f * x * (1.0f + erff(x * 0.70710678118654752f));
}

__device__ __forceinline__ float warp_sum(float v) {
    #pragma unroll
    for (int o = 16; o; o >>= 1) v += __shfl_down_sync(0xffffffffu, v, o);
    return v;
}

// ---------------------------------------------------------------------------
// Kernel 1: weighted-layer pooling + masked sum over an S-chunk.
// grid = (SPLIT, B), block = 256. Each thread owns 4 consecutive h (float4).
// ---------------------------------------------------------------------------
__global__ __launch_bounds__(256) void pool_kernel(
    const float* __restrict__ hidden,   // [L,B,S,H]
    const int*   __restrict__ mask,     // [B,S]
    const float* __restrict__ lw)       // [L]
{
    const int j = blockIdx.x;       // S-chunk
    const int b = blockIdx.y;
    const int t = threadIdx.x;      // 0..255

    float l0 = lw[0], l1 = lw[1], l2 = lw[2], l3 = lw[3];
    float mx = fmaxf(fmaxf(l0, l1), fmaxf(l2, l3));
    float w0 = expf(l0 - mx), w1 = expf(l1 - mx), w2 = expf(l2 - mx), w3 = expf(l3 - mx);
    float winv = 1.0f / (w0 + w1 + w2 + w3);
    w0 *= winv; w1 *= winv; w2 *= winv; w3 *= winv;

    __shared__ int sm[SROWS];
    if (t < SROWS) sm[t] = mask[b * Sc + j * SROWS + t];
    __syncthreads();

    const size_t LSTRIDE4 = (size_t)Bc * Sc * (Hc / 4);   // per-layer stride in float4
    const float4* base = reinterpret_cast<const float4*>(hidden)
                       + ((size_t)b * Sc + (size_t)j * SROWS) * (Hc / 4) + t;

    float4 acc = make_float4(0.f, 0.f, 0.f, 0.f);

    #pragma unroll 4
    for (int s = 0; s < SROWS; s++) {
        if (sm[s]) {
            const float4* p = base + (size_t)s * (Hc / 4);
            float4 x0 = __ldg(p);
            float4 x1 = __ldg(p + LSTRIDE4);
            float4 x2 = __ldg(p + 2 * LSTRIDE4);
            float4 x3 = __ldg(p + 3 * LSTRIDE4);
            acc.x += w0 * x0.x + w1 * x1.x + w2 * x2.x + w3 * x3.x;
            acc.y += w0 * x0.y + w1 * x1.y + w2 * x2.y + w3 * x3.y;
            acc.z += w0 * x0.z + w1 * x1.z + w2 * x2.z + w3 * x3.z;
            acc.w += w0 * x0.w + w1 * x1.w + w2 * x2.w + w3 * x3.w;
        }
    }

    reinterpret_cast<float4*>(g_partial)[((size_t)b * SPLIT + j) * (Hc / 4) + t] = acc;
}

// ---------------------------------------------------------------------------
// Kernel 2: per-sample finalize — 512 threads, all-float4 weight traffic.
// grid = B.
// ---------------------------------------------------------------------------
__global__ __launch_bounds__(512, 2) void finalize_kernel(
    const int*   __restrict__ mask,        // [B,S]
    const int*   __restrict__ section_id,  // [B]
    const float* __restrict__ Wd,          // [N_SEC,H,K]
    const float* __restrict__ bd,          // [N_SEC,K]
    const float* __restrict__ Wu,          // [N_SEC,K,H]
    const float* __restrict__ bu,          // [N_SEC,H]
    const float* __restrict__ Wreg,        // [H,1]
    const float* __restrict__ breg,        // [1]
    const float* __restrict__ Word,        // [H,4]
    const float* __restrict__ bord,        // [4]
    float*       __restrict__ out)         // [B] reg ++ [B,4] ord
{
    const int b = blockIdx.x;
    const int t = threadIdx.x;      // 0..511

    __shared__ float4 feats4[Hc / 4];      // 4 KB
    __shared__ float4 red4[32 * 16];       // 8 KB  (down-proj partials)
    __shared__ float4 acc_up[Hc / 4];      // 4 KB
    __shared__ float  hk[Kc];
    __shared__ float  redm[8];
    __shared__ float  wr[5][8];
    __shared__ float  invm_s;

    const float* feats = reinterpret_cast<const float*>(feats4);

    // ---- mask count (first 256 threads, one element each) ----
    if (t < Sc) {
        float mv = (float)mask[b * Sc + t];
        mv = warp_sum(mv);
        if ((t & 31) == 0) redm[t >> 5] = mv;
    }
    __syncthreads();
    if (t == 0) {
        float s = 0.f;
        #pragma unroll
        for (int i = 0; i < 8; i++) s += redm[i];
        invm_s = 1.0f / fmaxf(s, 1e-6f);
    }
    __syncthreads();
    const float invm = invm_s;

    // ---- gather partials -> feats (256 float4 columns) ----
    if (t < Hc / 4) {
        const float4* pp = reinterpret_cast<const float4*>(g_partial)
                         + (size_t)b * SPLIT * (Hc / 4) + t;
        float4 a = make_float4(0.f, 0.f, 0.f, 0.f);
        #pragma unroll
        for (int jj = 0; jj < SPLIT; jj++) {
            float4 x = pp[jj * (Hc / 4)];
            a.x += x.x; a.y += x.y; a.z += x.z; a.w += x.w;
        }
        a.x *= invm; a.y *= invm; a.z *= invm; a.w *= invm;
        feats4[t] = a;
    }
    __syncthreads();

    const int sec = section_id[b];

    // ---- down-proj: 512 threads = 16 k-quads x 32 h-groups ----
    {
        const int kq = t & 15;          // k4 index (k = 4*kq .. 4*kq+3)
        const int hg = t >> 4;          // 0..31
        const float4* wd4 = reinterpret_cast<const float4*>(Wd + (size_t)sec * Hc * Kc);
        float4 a = make_float4(0.f, 0.f, 0.f, 0.f);
        #pragma unroll 8
        for (int i = 0; i < 32; i++) {
            int h = hg * 32 + i;
            float f = feats[h];
            float4 w = __ldg(wd4 + (size_t)h * 16 + kq);
            a.x += f * w.x; a.y += f * w.y; a.z += f * w.z; a.w += f * w.w;
        }
        red4[hg * 16 + kq] = a;
    }
    __syncthreads();
    if (t < 16) {
        float4 s = make_float4(0.f, 0.f, 0.f, 0.f);
        #pragma unroll
        for (int hg = 0; hg < 32; hg++) {
            float4 x = red4[hg * 16 + t];
            s.x += x.x; s.y += x.y; s.z += x.z; s.w += x.w;
        }
        float4 bdv = __ldg(reinterpret_cast<const float4*>(bd + (size_t)sec * Kc) + t);
        hk[t * 4 + 0] = gelu_exact(s.x + bdv.x);
        hk[t * 4 + 1] = gelu_exact(s.y + bdv.y);
        hk[t * 4 + 2] = gelu_exact(s.z + bdv.z);
        hk[t * 4 + 3] = gelu_exact(s.w + bdv.w);
    }
    __syncthreads();

    // ---- up-proj: 256 h-quads x 2 k-halves ----
    const int c    = t & 255;           // h4 column (h = 4c..4c+3)
    const int half = t >> 8;            // 0 or 1
    const float4* wu4 = reinterpret_cast<const float4*>(Wu + (size_t)sec * Kc * Hc);
    float4 a = make_float4(0.f, 0.f, 0.f, 0.f);
    {
        const int k0 = half * 32;
        #pragma unroll 8
        for (int k = k0; k < k0 + 32; k++) {
            float hv = hk[k];
            float4 w = __ldg(wu4 + (size_t)k * (Hc / 4) + c);
            a.x += hv * w.x; a.y += hv * w.y; a.z += hv * w.z; a.w += hv * w.w;
        }
    }
    if (half == 0) acc_up[c] = a;
    __syncthreads();

    // ---- residual + heads (threads 256..511 only) ----
    if (half == 1) {
        float4 other = acc_up[c];
        float4 fv = feats4[c];
        float4 buv = __ldg(reinterpret_cast<const float4*>(bu + (size_t)sec * Hc) + c);
        float4 f2;
        f2.x = fv.x + buv.x + a.x + other.x;
        f2.y = fv.y + buv.y + a.y + other.y;
        f2.z = fv.z + buv.z + a.z + other.z;
        f2.w = fv.w + buv.w + a.w + other.w;

        float4 wrg = __ldg(reinterpret_cast<const float4*>(Wreg) + c);
        float preg = f2.x * wrg.x + f2.y * wrg.y + f2.z * wrg.z + f2.w * wrg.w;

        const float4* word4 = reinterpret_cast<const float4*>(Word);
        float4 w0 = __ldg(word4 + 4 * c + 0);
        float4 w1 = __ldg(word4 + 4 * c + 1);
        float4 w2 = __ldg(word4 + 4 * c + 2);
        float4 w3 = __ldg(word4 + 4 * c + 3);
        float po0 = f2.x * w0.x + f2.y * w1.x + f2.z * w2.x + f2.w * w3.x;
        float po1 = f2.x * w0.y + f2.y * w1.y + f2.z * w2.y + f2.w * w3.y;
        float po2 = f2.x * w0.z + f2.y * w1.z + f2.z * w2.z + f2.w * w3.z;
        float po3 = f2.x * w0.w + f2.y * w1.w + f2.z * w2.w + f2.w * w3.w;

        preg = warp_sum(preg);
        po0  = warp_sum(po0);
        po1  = warp_sum(po1);
        po2  = warp_sum(po2);
        po3  = warp_sum(po3);
        if ((c & 31) == 0) {
            int w = c >> 5;   // 0..7
            wr[0][w] = preg; wr[1][w] = po0; wr[2][w] = po1; wr[3][w] = po2; wr[4][w] = po3;
        }
    }
    __syncthreads();
    if (t == 0) {
        float r = 0.f, o0 = 0.f, o1 = 0.f, o2 = 0.f, o3 = 0.f;
        #pragma unroll
        for (int i = 0; i < 8; i++) {
            r  += wr[0][i]; o0 += wr[1][i]; o1 += wr[2][i]; o2 += wr[3][i]; o3 += wr[4][i];
        }
        out[b] = r + breg[0];
        float* op = out + Bc + (size_t)b * 4;
        op[0] = o0 + bord[0];
        op[1] = o1 + bord[1];
        op[2] = o2 + bord[2];
        op[3] = o3 + bord[3];
    }
}

extern "C" void kernel_launch(void* const* d_in, const int* in_sizes, int n_in,
                              void* d_out, int out_size)
{
    const float* hidden = (const float*)d_in[0];
    const int*   mask   = (const int*)  d_in[1];
    const int*   sec    = (const int*)  d_in[2];
    const float* lw     = (const float*)d_in[3];
    const float* Wd     = (const float*)d_in[4];
    const float* bd     = (const float*)d_in[5];
    const float* Wu     = (const float*)d_in[6];
    const float* bu     = (const float*)d_in[7];
    const float* Wreg   = (const float*)d_in[8];
    const float* breg   = (const float*)d_in[9];
    const float* Word   = (const float*)d_in[10];
    const float* bord   = (const float*)d_in[11];
    float* out = (float*)d_out;

    dim3 grid(SPLIT, Bc);
    pool_kernel<<<grid, 256>>>(hidden, mask, lw);
    finalize_kernel<<<Bc, 512>>>(mask, sec, Wd, bd, Wu, bu,
                                 Wreg, breg, Word, bord, out);
}